// round 2
// baseline (speedup 1.0000x reference)
#include <cuda_runtime.h>
#include <math.h>

#define NA   8192
#define NE   262144
#define NMOL 128
#define FF   128
#define RR   20
#define LL   3
#define PI_F 3.14159265358979f

// ---------------- scratch (device globals; no runtime alloc allowed) -------
__device__ float g_s  [NA * FF];
__device__ float g_vA [NA * 3 * FF];
__device__ float g_vB [NA * 3 * FF];
__device__ float g_h  [NA * FF];
__device__ float g_phi[NA * 3 * FF];
__device__ float g_uvv[NA * 3 * 2 * FF];      // fused [atom*3][256]: uv | vv
__device__ float g_cat[NA * 2 * FF];
__device__ float g_ah [NA * FF];
__device__ float g_a  [NA * 3 * FF];
__device__ float g_wuv[LL * FF * 2 * FF];     // concat upd_u|upd_v weights
__device__ float g_egeo[NE * 24];             // per sorted edge: rbf*fc[20], fc, unit[3]
__device__ int   g_esrc[NE];
__device__ int   g_rowstart[NA + 1];
__device__ int   g_cursor[NA];
__device__ int   g_count[NA];

// ---------------- packed f32x2 helpers --------------------------------------
__device__ __forceinline__ float2 ffma2(float2 a, float2 b, float2 c) {
    float2 d;
    asm("fma.rn.f32x2 %0, %1, %2, %3;"
        : "=l"(*reinterpret_cast<unsigned long long*>(&d))
        : "l"(*reinterpret_cast<unsigned long long*>(&a)),
          "l"(*reinterpret_cast<unsigned long long*>(&b)),
          "l"(*reinterpret_cast<unsigned long long*>(&c)));
    return d;
}
__device__ __forceinline__ float2 fmul2(float2 a, float2 b) {
    float2 d;
    asm("mul.rn.f32x2 %0, %1, %2;"
        : "=l"(*reinterpret_cast<unsigned long long*>(&d))
        : "l"(*reinterpret_cast<unsigned long long*>(&a)),
          "l"(*reinterpret_cast<unsigned long long*>(&b)));
    return d;
}

// ---------------- init / small kernels --------------------------------------
__global__ void init_kernel(float* vA, int* cnt, float* out) {
    int i = blockIdx.x * blockDim.x + threadIdx.x;
    if (i < NA) cnt[i] = 0;
    if (i < NMOL) out[i] = 0.f;
    for (int j = i; j < NA * 3 * FF; j += gridDim.x * blockDim.x) vA[j] = 0.f;
}

__global__ void embed_kernel(const int* __restrict__ z,
                             const float* __restrict__ embed,
                             float* __restrict__ s) {
    int i = blockIdx.x * blockDim.x + threadIdx.x;
    if (i >= NA * 32) return;
    int atom = i >> 5, q = i & 31;
    ((float4*)s)[i] = ((const float4*)(embed + (size_t)z[atom] * FF))[q];
}

__global__ void prep_uvw_kernel(const float* __restrict__ u,
                                const float* __restrict__ v,
                                float* __restrict__ w) {
    int i = blockIdx.x * blockDim.x + threadIdx.x;   // over LL*128*128
    if (i >= LL * FF * FF) return;
    int l = i / (FF * FF);
    int rem = i - l * FF * FF;
    int k = rem >> 7, n = rem & 127;
    size_t base = ((size_t)l * FF + k) * 2 * FF;
    w[base + n]      = u[i];
    w[base + FF + n] = v[i];
}

// ---------------- CSR build + edge geometry --------------------------------
__global__ void count_kernel(const int* __restrict__ dst, int* __restrict__ cnt) {
    int e = blockIdx.x * blockDim.x + threadIdx.x;
    if (e < NE) atomicAdd(&cnt[dst[e]], 1);
}

__global__ void scan_kernel(const int* __restrict__ cnt,
                            int* __restrict__ rowstart,
                            int* __restrict__ cursor) {
    __shared__ int part[1024];
    int t = threadIdx.x;                 // 1024 threads, 8 items each
    int loc[8], ex[8];
    int run = 0;
#pragma unroll
    for (int i = 0; i < 8; i++) {
        loc[i] = cnt[t * 8 + i];
        ex[i]  = run;
        run   += loc[i];
    }
    part[t] = run;
    __syncthreads();
    for (int off = 1; off < 1024; off <<= 1) {
        int v = (t >= off) ? part[t - off] : 0;
        __syncthreads();
        part[t] += v;
        __syncthreads();
    }
    int base = (t > 0) ? part[t - 1] : 0;
#pragma unroll
    for (int i = 0; i < 8; i++) {
        int rs = base + ex[i];
        rowstart[t * 8 + i] = rs;
        cursor[t * 8 + i]   = rs;
    }
    if (t == 1023) rowstart[NA] = part[1023];
}

__global__ void fill_kernel(const int* __restrict__ src,
                            const int* __restrict__ dst,
                            const float* __restrict__ pos,
                            int* __restrict__ cursor,
                            float* __restrict__ egeo,
                            int* __restrict__ esrc) {
    int e = blockIdx.x * blockDim.x + threadIdx.x;
    if (e >= NE) return;
    int sd = src[e], dd = dst[e];
    int p = atomicAdd(&cursor[dd], 1);
    float dx = pos[dd * 3 + 0] - pos[sd * 3 + 0];
    float dy = pos[dd * 3 + 1] - pos[sd * 3 + 1];
    float dz = pos[dd * 3 + 2] - pos[sd * 3 + 2];
    float d  = sqrtf(dx * dx + dy * dy + dz * dz + 1e-8f);
    float inv = 1.f / d;
    float fc = 0.5f * (cosf(PI_F * d / 5.0f) + 1.0f) * (d < 5.0f ? 1.f : 0.f);
    float* g = egeo + (size_t)p * 24;
#pragma unroll
    for (int r = 0; r < RR; r++) {
        float freq = (float)(r + 1) * (PI_F / 5.0f);
        g[r] = sinf(d * freq) * inv * fc;   // rbf * fc  (fc folded in)
    }
    g[20] = fc;
    g[21] = dx * inv; g[22] = dy * inv; g[23] = dz * inv;
    esrc[p] = sd;
}

// ---------------- fp32x2 GEMM: C = act(A[M,K] @ W[K,N] + bias) -------------
// BM=128, BN=64, BK=16, 256 threads, 8x4 per thread, f32x2 over row pairs.
template <bool SILU>
__global__ __launch_bounds__(256)
void gemm_kernel(const float* __restrict__ A, const float* __restrict__ W,
                 const float* __restrict__ bias, float* __restrict__ C,
                 int M, int N, int K) {
    __shared__ __align__(16) float As[16][128];
    __shared__ __align__(16) float Wd[16][128];   // duplicated {w,w} pairs, 64 cols
    int bn = blockIdx.x * 64;
    int bm = blockIdx.y * 128;
    int tid = threadIdx.x;
    int tx = tid & 15, ty = tid >> 4;
    float2 acc[4][4];
#pragma unroll
    for (int i = 0; i < 4; i++)
#pragma unroll
        for (int j = 0; j < 4; j++) acc[i][j] = make_float2(0.f, 0.f);

    for (int k0 = 0; k0 < K; k0 += 16) {
#pragma unroll
        for (int p = 0; p < 2; p++) {
            int idx = tid + p * 256;        // 0..511
            int row = idx >> 2;             // 0..127
            int kc  = (idx & 3) * 4;        // 0,4,8,12
            float4 va = *(const float4*)&A[(size_t)(bm + row) * K + k0 + kc];
            As[kc + 0][row] = va.x;
            As[kc + 1][row] = va.y;
            As[kc + 2][row] = va.z;
            As[kc + 3][row] = va.w;
        }
        {
            int kr = tid >> 4;              // 0..15
            int nc = (tid & 15) * 4;        // 0..60
            float4 vw = *(const float4*)&W[(size_t)(k0 + kr) * N + bn + nc];
            *(float4*)&Wd[kr][nc * 2]     = make_float4(vw.x, vw.x, vw.y, vw.y);
            *(float4*)&Wd[kr][nc * 2 + 4] = make_float4(vw.z, vw.z, vw.w, vw.w);
        }
        __syncthreads();
#pragma unroll
        for (int k = 0; k < 16; k++) {
            float2 a[4], b[4];
            *(float4*)&a[0] = *(const float4*)&As[k][ty * 8];
            *(float4*)&a[2] = *(const float4*)&As[k][ty * 8 + 4];
            *(float4*)&b[0] = *(const float4*)&Wd[k][tx * 8];
            *(float4*)&b[2] = *(const float4*)&Wd[k][tx * 8 + 4];
#pragma unroll
            for (int i = 0; i < 4; i++)
#pragma unroll
                for (int j = 0; j < 4; j++)
                    acc[i][j] = ffma2(a[i], b[j], acc[i][j]);
        }
        __syncthreads();
    }
    float4 bv = bias ? *(const float4*)&bias[bn + tx * 4]
                     : make_float4(0.f, 0.f, 0.f, 0.f);
    float bj[4] = {bv.x, bv.y, bv.z, bv.w};
#pragma unroll
    for (int i = 0; i < 4; i++) {
        float ox[4], oy[4];
#pragma unroll
        for (int j = 0; j < 4; j++) {
            float x0 = acc[i][j].x + bj[j];
            float x1 = acc[i][j].y + bj[j];
            if (SILU) {
                x0 = x0 / (1.f + __expf(-x0));
                x1 = x1 / (1.f + __expf(-x1));
            }
            ox[j] = x0; oy[j] = x1;
        }
        size_t base = (size_t)(bm + ty * 8 + 2 * i) * N + bn + tx * 4;
        *(float4*)&C[base]     = make_float4(ox[0], ox[1], ox[2], ox[3]);
        *(float4*)&C[base + N] = make_float4(oy[0], oy[1], oy[2], oy[3]);
    }
}

// ---------------- message pass (CSR gather, no atomics, f32x2) -------------
#define APB 4    // atoms per block
#define CH  16   // edges staged per chunk
__global__ __launch_bounds__(64)
void msg_kernel(const float* __restrict__ phi, const float* __restrict__ vin,
                float* __restrict__ s, float* __restrict__ vout,
                const float* __restrict__ rbfW, const float* __restrict__ rbfB,
                const float* __restrict__ egeo, const int* __restrict__ esrc,
                const int* __restrict__ rowstart) {
    int t = threadIdx.x;                  // 0..63, owns feature pair (2t, 2t+1)
    int f2 = t * 2;
    float2 w1[RR], w2[RR], w3[RR];
#pragma unroll
    for (int r = 0; r < RR; r++) {
        w1[r] = *(const float2*)&rbfW[r * 384 + f2];
        w2[r] = *(const float2*)&rbfW[r * 384 + 128 + f2];
        w3[r] = *(const float2*)&rbfW[r * 384 + 256 + f2];
    }
    float2 b1 = *(const float2*)&rbfB[f2];
    float2 b2 = *(const float2*)&rbfB[128 + f2];
    float2 b3 = *(const float2*)&rbfB[256 + f2];

    __shared__ float2 sG[CH][24];   // per-edge scalars duplicated {v,v}
    __shared__ int    sS[CH];

    int a0 = blockIdx.x * APB;
    for (int a = a0; a < a0 + APB; a++) {
        int beg = rowstart[a], end = rowstart[a + 1];
        float2 ds  = make_float2(0.f, 0.f);
        float2 dv0 = ds, dv1 = ds, dv2 = ds;
        for (int c0 = beg; c0 < end; c0 += CH) {
            int nc = min(CH, end - c0);
            __syncthreads();
            for (int i = t; i < nc * 24; i += 64) {
                float v = egeo[(size_t)c0 * 24 + i];
                sG[i / 24][i % 24] = make_float2(v, v);
            }
            if (t < nc) sS[t] = esrc[c0 + t];
            __syncthreads();
            for (int k = 0; k < nc; k++) {
                const float2* gk = sG[k];
                int src = sS[k];
                float2 fc = gk[20];
                float2 wf1 = fmul2(fc, b1);
                float2 wf2 = fmul2(fc, b2);
                float2 wf3 = fmul2(fc, b3);
#pragma unroll
                for (int r = 0; r < RR; r++) {
                    float2 rb = gk[r];
                    wf1 = ffma2(rb, w1[r], wf1);
                    wf2 = ffma2(rb, w2[r], wf2);
                    wf3 = ffma2(rb, w3[r], wf3);
                }
                const float* pb = phi + (size_t)src * 384;
                float2 p0 = *(const float2*)(pb + f2);
                float2 p1 = *(const float2*)(pb + 128 + f2);
                float2 p2 = *(const float2*)(pb + 256 + f2);
                ds = ffma2(p0, wf1, ds);
                float2 dvv = fmul2(p1, wf2);
                float2 dvs = fmul2(p2, wf3);
                const float* vb = vin + (size_t)src * 384;
                float2 v0 = *(const float2*)(vb + f2);
                float2 v1 = *(const float2*)(vb + 128 + f2);
                float2 v2 = *(const float2*)(vb + 256 + f2);
                dv0 = ffma2(v0, dvv, ffma2(gk[21], dvs, dv0));
                dv1 = ffma2(v1, dvv, ffma2(gk[22], dvs, dv1));
                dv2 = ffma2(v2, dvv, ffma2(gk[23], dvs, dv2));
            }
        }
        size_t sa = (size_t)a * 128 + f2;
        size_t va = (size_t)a * 384 + f2;
        float2 sv = *(float2*)&s[sa];
        sv.x += ds.x; sv.y += ds.y;
        *(float2*)&s[sa] = sv;
        float2 vi0 = *(const float2*)&vin[va];
        float2 vi1 = *(const float2*)&vin[va + 128];
        float2 vi2 = *(const float2*)&vin[va + 256];
        *(float2*)&vout[va]       = make_float2(vi0.x + dv0.x, vi0.y + dv0.y);
        *(float2*)&vout[va + 128] = make_float2(vi1.x + dv1.x, vi1.y + dv1.y);
        *(float2*)&vout[va + 256] = make_float2(vi2.x + dv2.x, vi2.y + dv2.y);
    }
}

// ---------------- per-atom update pieces ------------------------------------
// uvv layout: [atom*3 + c][256] with cols 0..127 = uv, 128..255 = vv
__global__ void cat_kernel(const float* __restrict__ s, const float* __restrict__ uvv,
                           float* __restrict__ cat) {
    int i = blockIdx.x * blockDim.x + threadIdx.x;
    if (i >= NA * FF) return;
    int atom = i >> 7, f = i & 127;
    size_t base = (size_t)atom * 3 * 256 + 128 + f;
    float x0 = uvv[base], x1 = uvv[base + 256], x2 = uvv[base + 512];
    float n = sqrtf(x0 * x0 + x1 * x1 + x2 * x2 + 1e-8f);
    cat[(size_t)atom * 256 + f]       = s[i];
    cat[(size_t)atom * 256 + 128 + f] = n;
}

__global__ void upd_kernel(const float* __restrict__ uvv,
                           const float* __restrict__ a,
                           float* __restrict__ s,
                           const float* __restrict__ vB, float* __restrict__ vA) {
    int i = blockIdx.x * blockDim.x + threadIdx.x;
    if (i >= NA * FF) return;
    int atom = i >> 7, f = i & 127;
    size_t ub = (size_t)atom * 3 * 256 + f;
    float u0 = uvv[ub],       u1 = uvv[ub + 256],       u2 = uvv[ub + 512];
    float x0 = uvv[ub + 128], x1 = uvv[ub + 384],       x2 = uvv[ub + 640];
    float dot = u0 * x0 + u1 * x1 + u2 * x2;
    size_t off = (size_t)atom * 384;
    float a_vv = a[off + f], a_sv = a[off + 128 + f], a_ss = a[off + 256 + f];
    s[i] += a_ss + a_sv * dot;
    vA[off + f]       = vB[off + f]       + a_vv * u0;
    vA[off + 128 + f] = vB[off + 128 + f] + a_vv * u1;
    vA[off + 256 + f] = vB[off + 256 + f] + a_vv * u2;
}

// ---------------- readout: GEMV + molecule segment sum ---------------------
__global__ void out2_kernel(const float* __restrict__ h, const float* __restrict__ w2,
                            const float* __restrict__ b2, const int* __restrict__ mol,
                            float* __restrict__ out) {
    int gw = (blockIdx.x * blockDim.x + threadIdx.x) >> 5;
    int lane = threadIdx.x & 31;
    if (gw >= NA) return;
    const float* hp = h + (size_t)gw * FF;
    float sum = 0.f;
#pragma unroll
    for (int i = lane; i < FF; i += 32) sum = fmaf(hp[i], w2[i], sum);
#pragma unroll
    for (int o = 16; o; o >>= 1) sum += __shfl_down_sync(0xffffffffu, sum, o);
    if (lane == 0) atomicAdd(&out[mol[gw]], sum + b2[0]);
}

// ---------------- host-side launch ------------------------------------------
static float* symf(const void* sym) {
    void* p = nullptr;
    cudaGetSymbolAddress(&p, sym);
    return (float*)p;
}
static int* symi(const void* sym) {
    void* p = nullptr;
    cudaGetSymbolAddress(&p, sym);
    return (int*)p;
}

extern "C" void kernel_launch(void* const* d_in, const int* in_sizes, int n_in,
                              void* d_out, int out_size) {
    const int*   z        = (const int*)  d_in[0];
    const float* pos      = (const float*)d_in[1];
    const int*   edge_src = (const int*)  d_in[2];
    const int*   edge_dst = (const int*)  d_in[3];
    const int*   mol_idx  = (const int*)  d_in[4];
    const float* embed    = (const float*)d_in[5];
    const float* msg_w1   = (const float*)d_in[6];
    const float* msg_b1   = (const float*)d_in[7];
    const float* msg_w2   = (const float*)d_in[8];
    const float* msg_b2   = (const float*)d_in[9];
    const float* rbf_w    = (const float*)d_in[10];
    const float* rbf_b    = (const float*)d_in[11];
    const float* upd_u    = (const float*)d_in[12];
    const float* upd_v    = (const float*)d_in[13];
    const float* upd_a1   = (const float*)d_in[14];
    const float* upd_a1b  = (const float*)d_in[15];
    const float* upd_a2   = (const float*)d_in[16];
    const float* upd_a2b  = (const float*)d_in[17];
    const float* out_w1   = (const float*)d_in[18];
    const float* out_b1   = (const float*)d_in[19];
    const float* out_w2   = (const float*)d_in[20];
    const float* out_b2   = (const float*)d_in[21];
    float* out = (float*)d_out;

    float* s    = symf(g_s);
    float* vA   = symf(g_vA);
    float* vB   = symf(g_vB);
    float* h    = symf(g_h);
    float* phi  = symf(g_phi);
    float* uvv  = symf(g_uvv);
    float* cat  = symf(g_cat);
    float* ah   = symf(g_ah);
    float* a    = symf(g_a);
    float* wuv  = symf(g_wuv);
    float* egeo = symf(g_egeo);
    int* esrc   = symi(g_esrc);
    int* rowst  = symi(g_rowstart);
    int* cursor = symi(g_cursor);
    int* count  = symi(g_count);

    // init
    init_kernel<<<1024, 256>>>(vA, count, out);
    embed_kernel<<<(NA * 32 + 255) / 256, 256>>>(z, embed, s);
    prep_uvw_kernel<<<(LL * FF * FF + 255) / 256, 256>>>(upd_u, upd_v, wuv);

    // CSR + edge geometry
    count_kernel<<<(NE + 255) / 256, 256>>>(edge_dst, count);
    scan_kernel<<<1, 1024>>>(count, rowst, cursor);
    fill_kernel<<<(NE + 255) / 256, 256>>>(edge_src, edge_dst, pos, cursor, egeo, esrc);

    for (int l = 0; l < LL; l++) {
        const float* w1  = msg_w1  + (size_t)l * FF * FF;
        const float* bb1 = msg_b1  + (size_t)l * FF;
        const float* w2  = msg_w2  + (size_t)l * FF * 3 * FF;
        const float* bb2 = msg_b2  + (size_t)l * 3 * FF;
        const float* rw  = rbf_w   + (size_t)l * RR * 3 * FF;
        const float* rb  = rbf_b   + (size_t)l * 3 * FF;
        const float* wl  = wuv     + (size_t)l * FF * 2 * FF;
        const float* a1  = upd_a1  + (size_t)l * 2 * FF * FF;
        const float* a1b = upd_a1b + (size_t)l * FF;
        const float* a2  = upd_a2  + (size_t)l * FF * 3 * FF;
        const float* a2b = upd_a2b + (size_t)l * 3 * FF;

        gemm_kernel<true ><<<dim3(2, 64),  256>>>(s,   w1, bb1, h,   NA, 128, 128);
        gemm_kernel<false><<<dim3(6, 64),  256>>>(h,   w2, bb2, phi, NA, 384, 128);
        msg_kernel<<<NA / APB, 64>>>(phi, vA, s, vB, rw, rb, egeo, esrc, rowst);
        gemm_kernel<false><<<dim3(4, 192), 256>>>(vB, wl, nullptr, uvv, NA * 3, 256, 128);
        cat_kernel<<<(NA * FF + 255) / 256, 256>>>(s, uvv, cat);
        gemm_kernel<true ><<<dim3(2, 64),  256>>>(cat, a1, a1b, ah, NA, 128, 256);
        gemm_kernel<false><<<dim3(6, 64),  256>>>(ah,  a2, a2b, a,  NA, 384, 128);
        upd_kernel<<<(NA * FF + 255) / 256, 256>>>(uvv, a, s, vB, vA);
    }

    gemm_kernel<true><<<dim3(2, 64), 256>>>(s, out_w1, out_b1, h, NA, 128, 128);
    out2_kernel<<<NA * 32 / 256, 256>>>(h, out_w2, out_b2, mol_idx, out);
}

// round 4
// speedup vs baseline: 1.7985x; 1.7985x over previous
#include <cuda_runtime.h>
#include <cuda_bf16.h>
#include <math.h>
#include <stdint.h>

#define NA   8192
#define NE   262144
#define NMOL 128
#define FF   128
#define RR   20
#define LL   3
#define PI_F 3.14159265358979f

// ---------------- scratch (device globals; no runtime alloc allowed) -------
__device__ float g_s  [NA * FF];
__device__ float g_vA [NA * 3 * FF];
__device__ float g_vB [NA * 3 * FF];
__device__ float g_h  [NA * FF];
__device__ float g_phi[NA * 3 * FF];
__device__ float g_uvv[NA * 3 * 2 * FF];      // fused [atom*3][256]: uv | vv
__device__ float g_cat[NA * 2 * FF];
__device__ float g_ah [NA * FF];
__device__ float g_a  [NA * 3 * FF];
__device__ float g_egeo[NE * 24];             // per sorted edge: rbf*fc[20], fc, unit[3]
__device__ int   g_esrc[NE];
__device__ int   g_rowstart[NA + 1];
__device__ int   g_cursor[NA];
__device__ int   g_count[NA];
// bf16 hi/lo weight blobs, N-major [n][k]
#define WBLOB_ELEMS (34 * 16384)
__device__ __nv_bfloat16 g_whi[WBLOB_ELEMS];
__device__ __nv_bfloat16 g_wlo[WBLOB_ELEMS];

// ---------------- init / small kernels --------------------------------------
__global__ void init_kernel(float* vA, int* cnt, float* out) {
    int i = blockIdx.x * blockDim.x + threadIdx.x;
    if (i < NA) cnt[i] = 0;
    if (i < NMOL) out[i] = 0.f;
    for (int j = i; j < NA * 3 * FF; j += gridDim.x * blockDim.x) vA[j] = 0.f;
}

__global__ void embed_kernel(const int* __restrict__ z,
                             const float* __restrict__ embed,
                             float* __restrict__ s) {
    int i = blockIdx.x * blockDim.x + threadIdx.x;
    if (i >= NA * 32) return;
    int atom = i >> 5, q = i & 31;
    ((float4*)s)[i] = ((const float4*)(embed + (size_t)z[atom] * FF))[q];
}

// weight prep: fp32 W[K][N] -> bf16 hi/lo at [n][K] (N-major, transposed)
__global__ void wprep_kernel(const float* __restrict__ W,
                             __nv_bfloat16* __restrict__ hi,
                             __nv_bfloat16* __restrict__ lo,
                             int K, int N) {
    int i = blockIdx.x * blockDim.x + threadIdx.x;
    if (i >= K * N) return;
    int k = i / N, n = i - k * N;
    float a = W[i];
    __nv_bfloat16 h = __float2bfloat16(a);
    __nv_bfloat16 l = __float2bfloat16(a - __bfloat162float(h));
    hi[(size_t)n * K + k] = h;
    lo[(size_t)n * K + k] = l;
}

// ---------------- CSR build + edge geometry --------------------------------
__global__ void count_kernel(const int* __restrict__ dst, int* __restrict__ cnt) {
    int e = blockIdx.x * blockDim.x + threadIdx.x;
    if (e < NE) atomicAdd(&cnt[dst[e]], 1);
}

__global__ void scan_kernel(const int* __restrict__ cnt,
                            int* __restrict__ rowstart,
                            int* __restrict__ cursor) {
    __shared__ int part[1024];
    int t = threadIdx.x;
    int loc[8], ex[8];
    int run = 0;
#pragma unroll
    for (int i = 0; i < 8; i++) {
        loc[i] = cnt[t * 8 + i];
        ex[i]  = run;
        run   += loc[i];
    }
    part[t] = run;
    __syncthreads();
    for (int off = 1; off < 1024; off <<= 1) {
        int v = (t >= off) ? part[t - off] : 0;
        __syncthreads();
        part[t] += v;
        __syncthreads();
    }
    int base = (t > 0) ? part[t - 1] : 0;
#pragma unroll
    for (int i = 0; i < 8; i++) {
        int rs = base + ex[i];
        rowstart[t * 8 + i] = rs;
        cursor[t * 8 + i]   = rs;
    }
    if (t == 1023) rowstart[NA] = part[1023];
}

__global__ void fill_kernel(const int* __restrict__ src,
                            const int* __restrict__ dst,
                            const float* __restrict__ pos,
                            int* __restrict__ cursor,
                            float* __restrict__ egeo,
                            int* __restrict__ esrc) {
    int e = blockIdx.x * blockDim.x + threadIdx.x;
    if (e >= NE) return;
    int sd = src[e], dd = dst[e];
    int p = atomicAdd(&cursor[dd], 1);
    float dx = pos[dd * 3 + 0] - pos[sd * 3 + 0];
    float dy = pos[dd * 3 + 1] - pos[sd * 3 + 1];
    float dz = pos[dd * 3 + 2] - pos[sd * 3 + 2];
    float d  = sqrtf(dx * dx + dy * dy + dz * dz + 1e-8f);
    float inv = 1.f / d;
    float fc = 0.5f * (cosf(PI_F * d / 5.0f) + 1.0f) * (d < 5.0f ? 1.f : 0.f);
    float* g = egeo + (size_t)p * 24;
#pragma unroll
    for (int r = 0; r < RR; r++) {
        float freq = (float)(r + 1) * (PI_F / 5.0f);
        g[r] = sinf(d * freq) * inv * fc;
    }
    g[20] = fc;
    g[21] = dx * inv; g[22] = dy * inv; g[23] = dz * inv;
    esrc[p] = sd;
}

// ---------------- HMMA bf16x2 GEMM ------------------------------------------
// C[M,N] = act(A[M,K] @ W[K,N] + bias); A fp32; W pre-split bf16 hi/lo [n][K].
// CTA tile 128(M)x64(N), 256 thr (8 warps as 4m x 2n, warp tile 32x32).
// mma.sync.m16n8k16 bf16 -> fp32, 3 passes (hi*hi, hi*lo, lo*hi).
#define GPAD 136
#define GT_SMEM ((2 * 128 + 2 * 64) * GPAD * 2)

__device__ __forceinline__ void mma16816(float* d, const uint32_t* a, const uint32_t* b) {
    asm volatile(
        "mma.sync.aligned.m16n8k16.row.col.f32.bf16.bf16.f32 "
        "{%0,%1,%2,%3}, {%4,%5,%6,%7}, {%8,%9}, {%0,%1,%2,%3};"
        : "+f"(d[0]), "+f"(d[1]), "+f"(d[2]), "+f"(d[3])
        : "r"(a[0]), "r"(a[1]), "r"(a[2]), "r"(a[3]), "r"(b[0]), "r"(b[1]));
}

template <bool SILU>
__global__ __launch_bounds__(256)
void gemm_mma(const float* __restrict__ A,
              const __nv_bfloat16* __restrict__ Whi,
              const __nv_bfloat16* __restrict__ Wlo,
              const float* __restrict__ bias, float* __restrict__ C,
              int M, int N, int K) {
    extern __shared__ __nv_bfloat16 sm[];
    __nv_bfloat16* Ahi = sm;
    __nv_bfloat16* Alo = sm + 128 * GPAD;
    __nv_bfloat16* Bhi = sm + 2 * 128 * GPAD;
    __nv_bfloat16* Blo = sm + 2 * 128 * GPAD + 64 * GPAD;

    int tid = threadIdx.x, wid = tid >> 5, lane = tid & 31;
    int bm = blockIdx.y << 7, bn = blockIdx.x << 6;
    int wm = (wid & 3) << 5, wn = (wid >> 2) << 5;
    int g = lane >> 2, tg = lane & 3;

    float d[2][4][4];
#pragma unroll
    for (int mt = 0; mt < 2; mt++)
#pragma unroll
        for (int nt = 0; nt < 4; nt++)
#pragma unroll
            for (int q = 0; q < 4; q++) d[mt][nt][q] = 0.f;

    for (int kc = 0; kc < K; kc += 128) {
        // stage A: fp32 -> bf16 hi/lo (128 x 128)
#pragma unroll
        for (int it = 0; it < 16; it++) {
            int idx = it * 256 + tid;          // 0..4095 float4s
            int r = idx >> 5, c = (idx & 31) << 2;
            float4 v = *(const float4*)&A[(size_t)(bm + r) * K + kc + c];
            __nv_bfloat16 h0 = __float2bfloat16(v.x);
            __nv_bfloat16 h1 = __float2bfloat16(v.y);
            __nv_bfloat16 h2 = __float2bfloat16(v.z);
            __nv_bfloat16 h3 = __float2bfloat16(v.w);
            __nv_bfloat16 l0 = __float2bfloat16(v.x - __bfloat162float(h0));
            __nv_bfloat16 l1 = __float2bfloat16(v.y - __bfloat162float(h1));
            __nv_bfloat16 l2 = __float2bfloat16(v.z - __bfloat162float(h2));
            __nv_bfloat16 l3 = __float2bfloat16(v.w - __bfloat162float(h3));
            uint32_t hp0 = ((uint32_t)__bfloat16_as_ushort(h1) << 16) | __bfloat16_as_ushort(h0);
            uint32_t hp1 = ((uint32_t)__bfloat16_as_ushort(h3) << 16) | __bfloat16_as_ushort(h2);
            uint32_t lp0 = ((uint32_t)__bfloat16_as_ushort(l1) << 16) | __bfloat16_as_ushort(l0);
            uint32_t lp1 = ((uint32_t)__bfloat16_as_ushort(l3) << 16) | __bfloat16_as_ushort(l2);
            *(uint32_t*)&Ahi[r * GPAD + c]     = hp0;
            *(uint32_t*)&Ahi[r * GPAD + c + 2] = hp1;
            *(uint32_t*)&Alo[r * GPAD + c]     = lp0;
            *(uint32_t*)&Alo[r * GPAD + c + 2] = lp1;
        }
        // stage B: flat bf16 copy (64 n-rows x 128 k)
#pragma unroll
        for (int it = 0; it < 4; it++) {
            int idx = it * 256 + tid;          // 0..1023 uint4s (8 bf16 each)
            int r = idx >> 4, c = (idx & 15) << 3;
            *(uint4*)&Bhi[r * GPAD + c] = *(const uint4*)&Whi[(size_t)(bn + r) * K + kc + c];
            *(uint4*)&Blo[r * GPAD + c] = *(const uint4*)&Wlo[(size_t)(bn + r) * K + kc + c];
        }
        __syncthreads();

#pragma unroll
        for (int ks = 0; ks < 8; ks++) {
            int k0 = ks * 16;
            uint32_t ah[2][4], al[2][4], bh[4][2], bl[4][2];
#pragma unroll
            for (int mt = 0; mt < 2; mt++) {
                int r0 = wm + mt * 16 + g;
                ah[mt][0] = *(uint32_t*)&Ahi[r0 * GPAD + k0 + tg * 2];
                ah[mt][1] = *(uint32_t*)&Ahi[(r0 + 8) * GPAD + k0 + tg * 2];
                ah[mt][2] = *(uint32_t*)&Ahi[r0 * GPAD + k0 + tg * 2 + 8];
                ah[mt][3] = *(uint32_t*)&Ahi[(r0 + 8) * GPAD + k0 + tg * 2 + 8];
                al[mt][0] = *(uint32_t*)&Alo[r0 * GPAD + k0 + tg * 2];
                al[mt][1] = *(uint32_t*)&Alo[(r0 + 8) * GPAD + k0 + tg * 2];
                al[mt][2] = *(uint32_t*)&Alo[r0 * GPAD + k0 + tg * 2 + 8];
                al[mt][3] = *(uint32_t*)&Alo[(r0 + 8) * GPAD + k0 + tg * 2 + 8];
            }
#pragma unroll
            for (int nt = 0; nt < 4; nt++) {
                int nr = wn + nt * 8 + g;
                bh[nt][0] = *(uint32_t*)&Bhi[nr * GPAD + k0 + tg * 2];
                bh[nt][1] = *(uint32_t*)&Bhi[nr * GPAD + k0 + tg * 2 + 8];
                bl[nt][0] = *(uint32_t*)&Blo[nr * GPAD + k0 + tg * 2];
                bl[nt][1] = *(uint32_t*)&Blo[nr * GPAD + k0 + tg * 2 + 8];
            }
#pragma unroll
            for (int mt = 0; mt < 2; mt++)
#pragma unroll
                for (int nt = 0; nt < 4; nt++) {
                    mma16816(d[mt][nt], ah[mt], bh[nt]);
                    mma16816(d[mt][nt], ah[mt], bl[nt]);
                    mma16816(d[mt][nt], al[mt], bh[nt]);
                }
        }
        __syncthreads();
    }

    // epilogue
#pragma unroll
    for (int mt = 0; mt < 2; mt++) {
        int row0 = bm + wm + mt * 16 + g;
#pragma unroll
        for (int nt = 0; nt < 4; nt++) {
            int col = bn + wn + nt * 8 + tg * 2;
            float b0 = 0.f, b1 = 0.f;
            if (bias) { b0 = bias[col]; b1 = bias[col + 1]; }
            float x0 = d[mt][nt][0] + b0, x1 = d[mt][nt][1] + b1;
            float x2 = d[mt][nt][2] + b0, x3 = d[mt][nt][3] + b1;
            if (SILU) {
                x0 = x0 / (1.f + __expf(-x0));
                x1 = x1 / (1.f + __expf(-x1));
                x2 = x2 / (1.f + __expf(-x2));
                x3 = x3 / (1.f + __expf(-x3));
            }
            *(float2*)&C[(size_t)row0 * N + col]       = make_float2(x0, x1);
            *(float2*)&C[(size_t)(row0 + 8) * N + col] = make_float2(x2, x3);
        }
    }
}

// ---------------- message pass (CSR gather, no atomics; R1 scalar) ---------
#define APB 4
#define CH  16
__global__ __launch_bounds__(128, 4)
void msg_kernel(const float* __restrict__ phi, const float* __restrict__ vin,
                float* __restrict__ s, float* __restrict__ vout,
                const float* __restrict__ rbfW, const float* __restrict__ rbfB,
                const float* __restrict__ egeo, const int* __restrict__ esrc,
                const int* __restrict__ rowstart) {
    int f = threadIdx.x;
    float w1[RR], w2[RR], w3[RR];
#pragma unroll
    for (int r = 0; r < RR; r++) {
        w1[r] = rbfW[r * 384 + f];
        w2[r] = rbfW[r * 384 + 128 + f];
        w3[r] = rbfW[r * 384 + 256 + f];
    }
    float b1 = rbfB[f], b2 = rbfB[128 + f], b3 = rbfB[256 + f];

    __shared__ float sG[CH * 24];
    __shared__ int   sS[CH];

    int a0 = blockIdx.x * APB;
    for (int a = a0; a < a0 + APB; a++) {
        int beg = rowstart[a], end = rowstart[a + 1];
        float ds = 0.f, dv0 = 0.f, dv1 = 0.f, dv2 = 0.f;
        for (int c0 = beg; c0 < end; c0 += CH) {
            int nc = min(CH, end - c0);
            __syncthreads();
            for (int t = f; t < nc * 24; t += 128)
                sG[t] = egeo[(size_t)c0 * 24 + t];
            if (f < nc) sS[f] = esrc[c0 + f];
            __syncthreads();
            for (int k = 0; k < nc; k++) {
                const float* gk = &sG[k * 24];
                float fc = gk[20];
                float u0 = gk[21], u1 = gk[22], u2 = gk[23];
                int src = sS[k];
                float wf1 = fc * b1, wf2 = fc * b2, wf3 = fc * b3;
#pragma unroll
                for (int r = 0; r < RR; r++) {
                    float rb = gk[r];
                    wf1 = fmaf(rb, w1[r], wf1);
                    wf2 = fmaf(rb, w2[r], wf2);
                    wf3 = fmaf(rb, w3[r], wf3);
                }
                const float* pp = phi + (size_t)src * 384;
                float m1  = pp[f]       * wf1;
                float dvv = pp[128 + f] * wf2;
                float dvs = pp[256 + f] * wf3;
                ds += m1;
                const float* vp = vin + (size_t)src * 384;
                dv0 = fmaf(vp[f],       dvv, fmaf(u0, dvs, dv0));
                dv1 = fmaf(vp[128 + f], dvv, fmaf(u1, dvs, dv1));
                dv2 = fmaf(vp[256 + f], dvv, fmaf(u2, dvs, dv2));
            }
        }
        size_t sa = (size_t)a * 128;
        size_t va = (size_t)a * 384;
        s[sa + f] += ds;
        vout[va + f]       = vin[va + f]       + dv0;
        vout[va + 128 + f] = vin[va + 128 + f] + dv1;
        vout[va + 256 + f] = vin[va + 256 + f] + dv2;
    }
}

// ---------------- per-atom update pieces ------------------------------------
// uvv layout: [atom*3 + c][256] with cols 0..127 = uv, 128..255 = vv
__global__ void cat_kernel(const float* __restrict__ s, const float* __restrict__ uvv,
                           float* __restrict__ cat) {
    int i = blockIdx.x * blockDim.x + threadIdx.x;
    if (i >= NA * FF) return;
    int atom = i >> 7, f = i & 127;
    size_t base = (size_t)atom * 3 * 256 + 128 + f;
    float x0 = uvv[base], x1 = uvv[base + 256], x2 = uvv[base + 512];
    float n = sqrtf(x0 * x0 + x1 * x1 + x2 * x2 + 1e-8f);
    cat[(size_t)atom * 256 + f]       = s[i];
    cat[(size_t)atom * 256 + 128 + f] = n;
}

__global__ void upd_kernel(const float* __restrict__ uvv,
                           const float* __restrict__ a,
                           float* __restrict__ s,
                           const float* __restrict__ vB, float* __restrict__ vA) {
    int i = blockIdx.x * blockDim.x + threadIdx.x;
    if (i >= NA * FF) return;
    int atom = i >> 7, f = i & 127;
    size_t ub = (size_t)atom * 3 * 256 + f;
    float u0 = uvv[ub],       u1 = uvv[ub + 256], u2 = uvv[ub + 512];
    float x0 = uvv[ub + 128], x1 = uvv[ub + 384], x2 = uvv[ub + 640];
    float dot = u0 * x0 + u1 * x1 + u2 * x2;
    size_t off = (size_t)atom * 384;
    float a_vv = a[off + f], a_sv = a[off + 128 + f], a_ss = a[off + 256 + f];
    s[i] += a_ss + a_sv * dot;
    vA[off + f]       = vB[off + f]       + a_vv * u0;
    vA[off + 128 + f] = vB[off + 128 + f] + a_vv * u1;
    vA[off + 256 + f] = vB[off + 256 + f] + a_vv * u2;
}

// ---------------- readout: GEMV + molecule segment sum ---------------------
__global__ void out2_kernel(const float* __restrict__ h, const float* __restrict__ w2,
                            const float* __restrict__ b2, const int* __restrict__ mol,
                            float* __restrict__ out) {
    int gw = (blockIdx.x * blockDim.x + threadIdx.x) >> 5;
    int lane = threadIdx.x & 31;
    if (gw >= NA) return;
    const float* hp = h + (size_t)gw * FF;
    float sum = 0.f;
#pragma unroll
    for (int i = lane; i < FF; i += 32) sum = fmaf(hp[i], w2[i], sum);
#pragma unroll
    for (int o = 16; o; o >>= 1) sum += __shfl_down_sync(0xffffffffu, sum, o);
    if (lane == 0) atomicAdd(&out[mol[gw]], sum + b2[0]);
}

// ---------------- host-side launch ------------------------------------------
static float* symf(const void* sym) {
    void* p = nullptr;
    cudaGetSymbolAddress(&p, sym);
    return (float*)p;
}
static int* symi(const void* sym) {
    void* p = nullptr;
    cudaGetSymbolAddress(&p, sym);
    return (int*)p;
}
static __nv_bfloat16* symb(const void* sym) {
    void* p = nullptr;
    cudaGetSymbolAddress(&p, sym);
    return (__nv_bfloat16*)p;
}

extern "C" void kernel_launch(void* const* d_in, const int* in_sizes, int n_in,
                              void* d_out, int out_size) {
    const int*   z        = (const int*)  d_in[0];
    const float* pos      = (const float*)d_in[1];
    const int*   edge_src = (const int*)  d_in[2];
    const int*   edge_dst = (const int*)  d_in[3];
    const int*   mol_idx  = (const int*)  d_in[4];
    const float* embed    = (const float*)d_in[5];
    const float* msg_w1   = (const float*)d_in[6];
    const float* msg_b1   = (const float*)d_in[7];
    const float* msg_w2   = (const float*)d_in[8];
    const float* msg_b2   = (const float*)d_in[9];
    const float* rbf_w    = (const float*)d_in[10];
    const float* rbf_b    = (const float*)d_in[11];
    const float* upd_u    = (const float*)d_in[12];
    const float* upd_v    = (const float*)d_in[13];
    const float* upd_a1   = (const float*)d_in[14];
    const float* upd_a1b  = (const float*)d_in[15];
    const float* upd_a2   = (const float*)d_in[16];
    const float* upd_a2b  = (const float*)d_in[17];
    const float* out_w1   = (const float*)d_in[18];
    const float* out_b1   = (const float*)d_in[19];
    const float* out_w2   = (const float*)d_in[20];
    const float* out_b2   = (const float*)d_in[21];
    float* out = (float*)d_out;

    float* s    = symf(g_s);
    float* vA   = symf(g_vA);
    float* vB   = symf(g_vB);
    float* h    = symf(g_h);
    float* phi  = symf(g_phi);
    float* uvv  = symf(g_uvv);
    float* cat  = symf(g_cat);
    float* ah   = symf(g_ah);
    float* a    = symf(g_a);
    float* egeo = symf(g_egeo);
    int* esrc   = symi(g_esrc);
    int* rowst  = symi(g_rowstart);
    int* cursor = symi(g_cursor);
    int* count  = symi(g_count);
    __nv_bfloat16* whi = symb(g_whi);
    __nv_bfloat16* wlo = symb(g_wlo);

    cudaFuncSetAttribute(gemm_mma<true>,  cudaFuncAttributeMaxDynamicSharedMemorySize, GT_SMEM);
    cudaFuncSetAttribute(gemm_mma<false>, cudaFuncAttributeMaxDynamicSharedMemorySize, GT_SMEM);

    // init
    init_kernel<<<1024, 256>>>(vA, count, out);
    embed_kernel<<<(NA * 32 + 255) / 256, 256>>>(z, embed, s);

    // weight prep blobs (elements, per layer LB = l*180224):
    //   w1@+0  w2@+16384  wuv@+65536 (u then v)  a1@+98304  a2@+131072
    //   out_w1 @ 540672
    for (int l = 0; l < LL; l++) {
        size_t LB = (size_t)l * 180224;
        wprep_kernel<<<(128 * 128 + 255) / 256, 256>>>(msg_w1 + (size_t)l * 16384,
            whi + LB, wlo + LB, 128, 128);
        wprep_kernel<<<(128 * 384 + 255) / 256, 256>>>(msg_w2 + (size_t)l * 49152,
            whi + LB + 16384, wlo + LB + 16384, 128, 384);
        wprep_kernel<<<(128 * 128 + 255) / 256, 256>>>(upd_u + (size_t)l * 16384,
            whi + LB + 65536, wlo + LB + 65536, 128, 128);
        wprep_kernel<<<(128 * 128 + 255) / 256, 256>>>(upd_v + (size_t)l * 16384,
            whi + LB + 65536 + 16384, wlo + LB + 65536 + 16384, 128, 128);
        wprep_kernel<<<(256 * 128 + 255) / 256, 256>>>(upd_a1 + (size_t)l * 32768,
            whi + LB + 98304, wlo + LB + 98304, 256, 128);
        wprep_kernel<<<(128 * 384 + 255) / 256, 256>>>(upd_a2 + (size_t)l * 49152,
            whi + LB + 131072, wlo + LB + 131072, 128, 384);
    }
    wprep_kernel<<<(128 * 128 + 255) / 256, 256>>>(out_w1,
        whi + 540672, wlo + 540672, 128, 128);

    // CSR + edge geometry
    count_kernel<<<(NE + 255) / 256, 256>>>(edge_dst, count);
    scan_kernel<<<1, 1024>>>(count, rowst, cursor);
    fill_kernel<<<(NE + 255) / 256, 256>>>(edge_src, edge_dst, pos, cursor, egeo, esrc);

    for (int l = 0; l < LL; l++) {
        size_t LB = (size_t)l * 180224;
        const float* bb1 = msg_b1  + (size_t)l * FF;
        const float* bb2 = msg_b2  + (size_t)l * 3 * FF;
        const float* rw  = rbf_w   + (size_t)l * RR * 3 * FF;
        const float* rb  = rbf_b   + (size_t)l * 3 * FF;
        const float* a1b = upd_a1b + (size_t)l * FF;
        const float* a2b = upd_a2b + (size_t)l * 3 * FF;

        gemm_mma<true ><<<dim3(2, 64),  256, GT_SMEM>>>(s,   whi + LB,          wlo + LB,          bb1,     h,   NA, 128, 128);
        gemm_mma<false><<<dim3(6, 64),  256, GT_SMEM>>>(h,   whi + LB + 16384,  wlo + LB + 16384,  bb2,     phi, NA, 384, 128);
        msg_kernel<<<NA / APB, 128>>>(phi, vA, s, vB, rw, rb, egeo, esrc, rowst);
        gemm_mma<false><<<dim3(4, 192), 256, GT_SMEM>>>(vB,  whi + LB + 65536,  wlo + LB + 65536,  nullptr, uvv, NA * 3, 256, 128);
        cat_kernel<<<(NA * FF + 255) / 256, 256>>>(s, uvv, cat);
        gemm_mma<true ><<<dim3(2, 64),  256, GT_SMEM>>>(cat, whi + LB + 98304,  wlo + LB + 98304,  a1b,     ah,  NA, 128, 256);
        gemm_mma<false><<<dim3(6, 64),  256, GT_SMEM>>>(ah,  whi + LB + 131072, wlo + LB + 131072, a2b,     a,   NA, 384, 128);
        upd_kernel<<<(NA * FF + 255) / 256, 256>>>(uvv, a, s, vB, vA);
    }

    gemm_mma<true><<<dim3(2, 64), 256, GT_SMEM>>>(s, whi + 540672, wlo + 540672, out_b1, h, NA, 128, 128);
    out2_kernel<<<NA * 32 / 256, 256>>>(h, out_w2, out_b2, mol_idx, out);
}

// round 5
// speedup vs baseline: 1.8486x; 1.0279x over previous
#include <cuda_runtime.h>
#include <cuda_bf16.h>
#include <math.h>
#include <stdint.h>

#define NA   8192
#define NE   262144
#define NMOL 128
#define FF   128
#define RR   20
#define LL   3
#define PI_F 3.14159265358979f

// ---------------- scratch (device globals; no runtime alloc allowed) -------
__device__ float g_s  [NA * FF];
__device__ float g_vA [NA * 3 * FF];
__device__ float g_vB [NA * 3 * FF];
__device__ float g_h  [NA * FF];
__device__ float g_phi[NA * 3 * FF];
__device__ float g_uvv[NA * 3 * 2 * FF];      // fused [atom*3][256]: uv | vv
__device__ float g_cat[NA * 2 * FF];
__device__ float g_ah [NA * FF];
__device__ float g_a  [NA * 3 * FF];
__device__ float g_egeo[NE * 24];             // per sorted edge: rbf*fc[20], fc, unit[3]
__device__ int   g_esrc[NE];
__device__ int   g_rowstart[NA + 1];
__device__ int   g_cursor[NA];
__device__ int   g_count[NA];
// bf16 hi/lo weight blobs, N-major [n][k]
#define WBLOB_ELEMS (34 * 16384)
__device__ __nv_bfloat16 g_whi[WBLOB_ELEMS];
__device__ __nv_bfloat16 g_wlo[WBLOB_ELEMS];

// ---------------- packed f32x2 helpers --------------------------------------
__device__ __forceinline__ float2 ffma2(float2 a, float2 b, float2 c) {
    float2 d;
    asm("fma.rn.f32x2 %0, %1, %2, %3;"
        : "=l"(*reinterpret_cast<unsigned long long*>(&d))
        : "l"(*reinterpret_cast<unsigned long long*>(&a)),
          "l"(*reinterpret_cast<unsigned long long*>(&b)),
          "l"(*reinterpret_cast<unsigned long long*>(&c)));
    return d;
}
__device__ __forceinline__ float2 fmul2(float2 a, float2 b) {
    float2 d;
    asm("mul.rn.f32x2 %0, %1, %2;"
        : "=l"(*reinterpret_cast<unsigned long long*>(&d))
        : "l"(*reinterpret_cast<unsigned long long*>(&a)),
          "l"(*reinterpret_cast<unsigned long long*>(&b)));
    return d;
}
__device__ __forceinline__ float2 fadd2(float2 a, float2 b) {
    float2 d;
    asm("add.rn.f32x2 %0, %1, %2;"
        : "=l"(*reinterpret_cast<unsigned long long*>(&d))
        : "l"(*reinterpret_cast<unsigned long long*>(&a)),
          "l"(*reinterpret_cast<unsigned long long*>(&b)));
    return d;
}

// ---------------- init / small kernels --------------------------------------
__global__ void init_kernel(int* cnt, float* out) {
    int i = blockIdx.x * blockDim.x + threadIdx.x;
    if (i < NA) cnt[i] = 0;
    if (i < NMOL) out[i] = 0.f;
}

__global__ void embed_kernel(const int* __restrict__ z,
                             const float* __restrict__ embed,
                             float* __restrict__ s) {
    int i = blockIdx.x * blockDim.x + threadIdx.x;
    if (i >= NA * 32) return;
    int atom = i >> 5, q = i & 31;
    ((float4*)s)[i] = ((const float4*)(embed + (size_t)z[atom] * FF))[q];
}

// one-shot weight prep: fp32 W[K][N] -> bf16 hi/lo at [n][K] (transposed),
// all 19 weight matrices in one launch.
// Per-layer blob (elements): w1@0 w2@16384 u@65536 v@81920 a1@98304 a2@131072
// out_w1 @ 540672. Total 557056.
__global__ void wprep_all(const float* __restrict__ msg_w1,
                          const float* __restrict__ msg_w2,
                          const float* __restrict__ upd_u,
                          const float* __restrict__ upd_v,
                          const float* __restrict__ upd_a1,
                          const float* __restrict__ upd_a2,
                          const float* __restrict__ out_w1,
                          __nv_bfloat16* __restrict__ hi,
                          __nv_bfloat16* __restrict__ lo) {
    int i = blockIdx.x * blockDim.x + threadIdx.x;
    if (i >= 557056) return;
    const float* src;
    int K, N, idx, segbase;
    if (i >= 540672) {
        src = out_w1; K = 128; N = 128; idx = i - 540672; segbase = 540672;
    } else {
        int l = i / 180224;
        int r = i - l * 180224;
        if (r < 16384)       { src = msg_w1 + l * 16384; K = 128; N = 128; idx = r;          segbase = l * 180224; }
        else if (r < 65536)  { src = msg_w2 + l * 49152; K = 128; N = 384; idx = r - 16384;  segbase = l * 180224 + 16384; }
        else if (r < 81920)  { src = upd_u  + l * 16384; K = 128; N = 128; idx = r - 65536;  segbase = l * 180224 + 65536; }
        else if (r < 98304)  { src = upd_v  + l * 16384; K = 128; N = 128; idx = r - 81920;  segbase = l * 180224 + 81920; }
        else if (r < 131072) { src = upd_a1 + l * 32768; K = 256; N = 128; idx = r - 98304;  segbase = l * 180224 + 98304; }
        else                 { src = upd_a2 + l * 49152; K = 128; N = 384; idx = r - 131072; segbase = l * 180224 + 131072; }
    }
    int k = idx / N, n = idx - k * N;
    float a = src[idx];
    __nv_bfloat16 h = __float2bfloat16(a);
    __nv_bfloat16 l2 = __float2bfloat16(a - __bfloat162float(h));
    hi[(size_t)segbase + (size_t)n * K + k] = h;
    lo[(size_t)segbase + (size_t)n * K + k] = l2;
}

// ---------------- CSR build + edge geometry --------------------------------
__global__ void count_kernel(const int* __restrict__ dst, int* __restrict__ cnt) {
    int e = blockIdx.x * blockDim.x + threadIdx.x;
    if (e < NE) atomicAdd(&cnt[dst[e]], 1);
}

__global__ void scan_kernel(const int* __restrict__ cnt,
                            int* __restrict__ rowstart,
                            int* __restrict__ cursor) {
    __shared__ int part[1024];
    int t = threadIdx.x;
    int loc[8], ex[8];
    int run = 0;
#pragma unroll
    for (int i = 0; i < 8; i++) {
        loc[i] = cnt[t * 8 + i];
        ex[i]  = run;
        run   += loc[i];
    }
    part[t] = run;
    __syncthreads();
    for (int off = 1; off < 1024; off <<= 1) {
        int v = (t >= off) ? part[t - off] : 0;
        __syncthreads();
        part[t] += v;
        __syncthreads();
    }
    int base = (t > 0) ? part[t - 1] : 0;
#pragma unroll
    for (int i = 0; i < 8; i++) {
        int rs = base + ex[i];
        rowstart[t * 8 + i] = rs;
        cursor[t * 8 + i]   = rs;
    }
    if (t == 1023) rowstart[NA] = part[1023];
}

__global__ void fill_kernel(const int* __restrict__ src,
                            const int* __restrict__ dst,
                            const float* __restrict__ pos,
                            int* __restrict__ cursor,
                            float* __restrict__ egeo,
                            int* __restrict__ esrc) {
    int e = blockIdx.x * blockDim.x + threadIdx.x;
    if (e >= NE) return;
    int sd = src[e], dd = dst[e];
    int p = atomicAdd(&cursor[dd], 1);
    float dx = pos[dd * 3 + 0] - pos[sd * 3 + 0];
    float dy = pos[dd * 3 + 1] - pos[sd * 3 + 1];
    float dz = pos[dd * 3 + 2] - pos[sd * 3 + 2];
    float d  = sqrtf(dx * dx + dy * dy + dz * dz + 1e-8f);
    float inv = 1.f / d;
    float fc = 0.5f * (cosf(PI_F * d / 5.0f) + 1.0f) * (d < 5.0f ? 1.f : 0.f);
    float* g = egeo + (size_t)p * 24;
#pragma unroll
    for (int r = 0; r < RR; r++) {
        float freq = (float)(r + 1) * (PI_F / 5.0f);
        g[r] = sinf(d * freq) * inv * fc;
    }
    g[20] = fc;
    g[21] = dx * inv; g[22] = dy * inv; g[23] = dz * inv;
    esrc[p] = sd;
}

// ---------------- HMMA bf16x2 GEMM (unchanged from R4) ----------------------
#define GPAD 136
#define GT_SMEM ((2 * 128 + 2 * 64) * GPAD * 2)

__device__ __forceinline__ void mma16816(float* d, const uint32_t* a, const uint32_t* b) {
    asm volatile(
        "mma.sync.aligned.m16n8k16.row.col.f32.bf16.bf16.f32 "
        "{%0,%1,%2,%3}, {%4,%5,%6,%7}, {%8,%9}, {%0,%1,%2,%3};"
        : "+f"(d[0]), "+f"(d[1]), "+f"(d[2]), "+f"(d[3])
        : "r"(a[0]), "r"(a[1]), "r"(a[2]), "r"(a[3]), "r"(b[0]), "r"(b[1]));
}

template <bool SILU>
__global__ __launch_bounds__(256)
void gemm_mma(const float* __restrict__ A,
              const __nv_bfloat16* __restrict__ Whi,
              const __nv_bfloat16* __restrict__ Wlo,
              const float* __restrict__ bias, float* __restrict__ C,
              int M, int N, int K) {
    extern __shared__ __nv_bfloat16 sm[];
    __nv_bfloat16* Ahi = sm;
    __nv_bfloat16* Alo = sm + 128 * GPAD;
    __nv_bfloat16* Bhi = sm + 2 * 128 * GPAD;
    __nv_bfloat16* Blo = sm + 2 * 128 * GPAD + 64 * GPAD;

    int tid = threadIdx.x, wid = tid >> 5, lane = tid & 31;
    int bm = blockIdx.y << 7, bn = blockIdx.x << 6;
    int wm = (wid & 3) << 5, wn = (wid >> 2) << 5;
    int g = lane >> 2, tg = lane & 3;

    float d[2][4][4];
#pragma unroll
    for (int mt = 0; mt < 2; mt++)
#pragma unroll
        for (int nt = 0; nt < 4; nt++)
#pragma unroll
            for (int q = 0; q < 4; q++) d[mt][nt][q] = 0.f;

    for (int kc = 0; kc < K; kc += 128) {
#pragma unroll
        for (int it = 0; it < 16; it++) {
            int idx = it * 256 + tid;
            int r = idx >> 5, c = (idx & 31) << 2;
            float4 v = *(const float4*)&A[(size_t)(bm + r) * K + kc + c];
            __nv_bfloat16 h0 = __float2bfloat16(v.x);
            __nv_bfloat16 h1 = __float2bfloat16(v.y);
            __nv_bfloat16 h2 = __float2bfloat16(v.z);
            __nv_bfloat16 h3 = __float2bfloat16(v.w);
            __nv_bfloat16 l0 = __float2bfloat16(v.x - __bfloat162float(h0));
            __nv_bfloat16 l1 = __float2bfloat16(v.y - __bfloat162float(h1));
            __nv_bfloat16 l2 = __float2bfloat16(v.z - __bfloat162float(h2));
            __nv_bfloat16 l3 = __float2bfloat16(v.w - __bfloat162float(h3));
            uint32_t hp0 = ((uint32_t)__bfloat16_as_ushort(h1) << 16) | __bfloat16_as_ushort(h0);
            uint32_t hp1 = ((uint32_t)__bfloat16_as_ushort(h3) << 16) | __bfloat16_as_ushort(h2);
            uint32_t lp0 = ((uint32_t)__bfloat16_as_ushort(l1) << 16) | __bfloat16_as_ushort(l0);
            uint32_t lp1 = ((uint32_t)__bfloat16_as_ushort(l3) << 16) | __bfloat16_as_ushort(l2);
            *(uint32_t*)&Ahi[r * GPAD + c]     = hp0;
            *(uint32_t*)&Ahi[r * GPAD + c + 2] = hp1;
            *(uint32_t*)&Alo[r * GPAD + c]     = lp0;
            *(uint32_t*)&Alo[r * GPAD + c + 2] = lp1;
        }
#pragma unroll
        for (int it = 0; it < 4; it++) {
            int idx = it * 256 + tid;
            int r = idx >> 4, c = (idx & 15) << 3;
            *(uint4*)&Bhi[r * GPAD + c] = *(const uint4*)&Whi[(size_t)(bn + r) * K + kc + c];
            *(uint4*)&Blo[r * GPAD + c] = *(const uint4*)&Wlo[(size_t)(bn + r) * K + kc + c];
        }
        __syncthreads();

#pragma unroll
        for (int ks = 0; ks < 8; ks++) {
            int k0 = ks * 16;
            uint32_t ah[2][4], al[2][4], bh[4][2], bl[4][2];
#pragma unroll
            for (int mt = 0; mt < 2; mt++) {
                int r0 = wm + mt * 16 + g;
                ah[mt][0] = *(uint32_t*)&Ahi[r0 * GPAD + k0 + tg * 2];
                ah[mt][1] = *(uint32_t*)&Ahi[(r0 + 8) * GPAD + k0 + tg * 2];
                ah[mt][2] = *(uint32_t*)&Ahi[r0 * GPAD + k0 + tg * 2 + 8];
                ah[mt][3] = *(uint32_t*)&Ahi[(r0 + 8) * GPAD + k0 + tg * 2 + 8];
                al[mt][0] = *(uint32_t*)&Alo[r0 * GPAD + k0 + tg * 2];
                al[mt][1] = *(uint32_t*)&Alo[(r0 + 8) * GPAD + k0 + tg * 2];
                al[mt][2] = *(uint32_t*)&Alo[r0 * GPAD + k0 + tg * 2 + 8];
                al[mt][3] = *(uint32_t*)&Alo[(r0 + 8) * GPAD + k0 + tg * 2 + 8];
            }
#pragma unroll
            for (int nt = 0; nt < 4; nt++) {
                int nr = wn + nt * 8 + g;
                bh[nt][0] = *(uint32_t*)&Bhi[nr * GPAD + k0 + tg * 2];
                bh[nt][1] = *(uint32_t*)&Bhi[nr * GPAD + k0 + tg * 2 + 8];
                bl[nt][0] = *(uint32_t*)&Blo[nr * GPAD + k0 + tg * 2];
                bl[nt][1] = *(uint32_t*)&Blo[nr * GPAD + k0 + tg * 2 + 8];
            }
#pragma unroll
            for (int mt = 0; mt < 2; mt++)
#pragma unroll
                for (int nt = 0; nt < 4; nt++) {
                    mma16816(d[mt][nt], ah[mt], bh[nt]);
                    mma16816(d[mt][nt], ah[mt], bl[nt]);
                    mma16816(d[mt][nt], al[mt], bh[nt]);
                }
        }
        __syncthreads();
    }

#pragma unroll
    for (int mt = 0; mt < 2; mt++) {
        int row0 = bm + wm + mt * 16 + g;
#pragma unroll
        for (int nt = 0; nt < 4; nt++) {
            int col = bn + wn + nt * 8 + tg * 2;
            float b0 = 0.f, b1 = 0.f;
            if (bias) { b0 = bias[col]; b1 = bias[col + 1]; }
            float x0 = d[mt][nt][0] + b0, x1 = d[mt][nt][1] + b1;
            float x2 = d[mt][nt][2] + b0, x3 = d[mt][nt][3] + b1;
            if (SILU) {
                x0 = x0 / (1.f + __expf(-x0));
                x1 = x1 / (1.f + __expf(-x1));
                x2 = x2 / (1.f + __expf(-x2));
                x3 = x3 / (1.f + __expf(-x3));
            }
            *(float2*)&C[(size_t)row0 * N + col]       = make_float2(x0, x1);
            *(float2*)&C[(size_t)(row0 + 8) * N + col] = make_float2(x2, x3);
        }
    }
}

// ---------------- message pass (CSR gather, f32x2 feature pairs) ------------
#define APB 4
#define CH  32
template <bool FIRST>
__global__ __launch_bounds__(64)
void msg_kernel(const float* __restrict__ phi, const float* __restrict__ vin,
                float* __restrict__ s, float* __restrict__ vout,
                const float* __restrict__ rbfW, const float* __restrict__ rbfB,
                const float* __restrict__ egeo, const int* __restrict__ esrc,
                const int* __restrict__ rowstart) {
    int t = threadIdx.x;                  // owns feature pair (2t, 2t+1)
    int f2 = t * 2;
    float2 w1[RR], w2[RR], w3[RR];
#pragma unroll
    for (int r = 0; r < RR; r++) {
        w1[r] = *(const float2*)&rbfW[r * 384 + f2];
        if (!FIRST) w2[r] = *(const float2*)&rbfW[r * 384 + 128 + f2];
        w3[r] = *(const float2*)&rbfW[r * 384 + 256 + f2];
    }
    float2 b1 = *(const float2*)&rbfB[f2];
    float2 b2 = FIRST ? make_float2(0.f, 0.f) : *(const float2*)&rbfB[128 + f2];
    float2 b3 = *(const float2*)&rbfB[256 + f2];

    __shared__ float2 sG[CH][24];   // per-edge scalars duplicated {v,v}
    __shared__ int    sS[CH];

    int a0 = blockIdx.x * APB;
    for (int a = a0; a < a0 + APB; a++) {
        int beg = rowstart[a], end = rowstart[a + 1];
        float2 ds  = make_float2(0.f, 0.f);
        float2 dv0 = ds, dv1 = ds, dv2 = ds;
        for (int c0 = beg; c0 < end; c0 += CH) {
            int nc = min(CH, end - c0);
            __syncthreads();
            for (int i = t; i < nc * 24; i += 64) {
                float v = egeo[(size_t)c0 * 24 + i];
                sG[i / 24][i % 24] = make_float2(v, v);
            }
            if (t < nc) sS[t] = esrc[c0 + t];
            __syncthreads();
            for (int k = 0; k < nc; k++) {
                const float2* gk = sG[k];
                int src = sS[k];
                // issue gathers first: their latency hides under the filter chain
                const float* pb = phi + (size_t)src * 384;
                float2 p0 = *(const float2*)(pb + f2);
                float2 p1, p2;
                p2 = *(const float2*)(pb + 256 + f2);
                float2 v0, v1, v2;
                if (!FIRST) {
                    p1 = *(const float2*)(pb + 128 + f2);
                    const float* vb = vin + (size_t)src * 384;
                    v0 = *(const float2*)(vb + f2);
                    v1 = *(const float2*)(vb + 128 + f2);
                    v2 = *(const float2*)(vb + 256 + f2);
                }
                float2 fc = gk[20];
                float2 wf1 = fmul2(fc, b1);
                float2 wf2 = FIRST ? make_float2(0.f, 0.f) : fmul2(fc, b2);
                float2 wf3 = fmul2(fc, b3);
#pragma unroll
                for (int r = 0; r < RR; r++) {
                    float2 rb = gk[r];
                    wf1 = ffma2(rb, w1[r], wf1);
                    if (!FIRST) wf2 = ffma2(rb, w2[r], wf2);
                    wf3 = ffma2(rb, w3[r], wf3);
                }
                ds = ffma2(p0, wf1, ds);
                float2 dvs = fmul2(p2, wf3);
                dv0 = ffma2(gk[21], dvs, dv0);
                dv1 = ffma2(gk[22], dvs, dv1);
                dv2 = ffma2(gk[23], dvs, dv2);
                if (!FIRST) {
                    float2 dvv = fmul2(p1, wf2);
                    dv0 = ffma2(v0, dvv, dv0);
                    dv1 = ffma2(v1, dvv, dv1);
                    dv2 = ffma2(v2, dvv, dv2);
                }
            }
        }
        size_t sa = (size_t)a * 128 + f2;
        size_t va = (size_t)a * 384 + f2;
        *(float2*)&s[sa] = fadd2(*(const float2*)&s[sa], ds);
        if (FIRST) {
            *(float2*)&vout[va]       = dv0;
            *(float2*)&vout[va + 128] = dv1;
            *(float2*)&vout[va + 256] = dv2;
        } else {
            *(float2*)&vout[va]       = fadd2(*(const float2*)&vin[va],       dv0);
            *(float2*)&vout[va + 128] = fadd2(*(const float2*)&vin[va + 128], dv1);
            *(float2*)&vout[va + 256] = fadd2(*(const float2*)&vin[va + 256], dv2);
        }
    }
}

// ---------------- per-atom update pieces ------------------------------------
// uvv layout: [atom*3 + c][256] with cols 0..127 = uv, 128..255 = vv
__global__ void cat_kernel(const float* __restrict__ s, const float* __restrict__ uvv,
                           float* __restrict__ cat) {
    int i = blockIdx.x * blockDim.x + threadIdx.x;
    if (i >= NA * FF) return;
    int atom = i >> 7, f = i & 127;
    size_t base = (size_t)atom * 3 * 256 + 128 + f;
    float x0 = uvv[base], x1 = uvv[base + 256], x2 = uvv[base + 512];
    float n = sqrtf(x0 * x0 + x1 * x1 + x2 * x2 + 1e-8f);
    cat[(size_t)atom * 256 + f]       = s[i];
    cat[(size_t)atom * 256 + 128 + f] = n;
}

__global__ void upd_kernel(const float* __restrict__ uvv,
                           const float* __restrict__ a,
                           float* __restrict__ s,
                           const float* __restrict__ vB, float* __restrict__ vA) {
    int i = blockIdx.x * blockDim.x + threadIdx.x;
    if (i >= NA * FF) return;
    int atom = i >> 7, f = i & 127;
    size_t ub = (size_t)atom * 3 * 256 + f;
    float u0 = uvv[ub],       u1 = uvv[ub + 256], u2 = uvv[ub + 512];
    float x0 = uvv[ub + 128], x1 = uvv[ub + 384], x2 = uvv[ub + 640];
    float dot = u0 * x0 + u1 * x1 + u2 * x2;
    size_t off = (size_t)atom * 384;
    float a_vv = a[off + f], a_sv = a[off + 128 + f], a_ss = a[off + 256 + f];
    s[i] += a_ss + a_sv * dot;
    vA[off + f]       = vB[off + f]       + a_vv * u0;
    vA[off + 128 + f] = vB[off + 128 + f] + a_vv * u1;
    vA[off + 256 + f] = vB[off + 256 + f] + a_vv * u2;
}

// ---------------- readout: GEMV + molecule segment sum ---------------------
__global__ void out2_kernel(const float* __restrict__ h, const float* __restrict__ w2,
                            const float* __restrict__ b2, const int* __restrict__ mol,
                            float* __restrict__ out) {
    int gw = (blockIdx.x * blockDim.x + threadIdx.x) >> 5;
    int lane = threadIdx.x & 31;
    if (gw >= NA) return;
    const float* hp = h + (size_t)gw * FF;
    float sum = 0.f;
#pragma unroll
    for (int i = lane; i < FF; i += 32) sum = fmaf(hp[i], w2[i], sum);
#pragma unroll
    for (int o = 16; o; o >>= 1) sum += __shfl_down_sync(0xffffffffu, sum, o);
    if (lane == 0) atomicAdd(&out[mol[gw]], sum + b2[0]);
}

// ---------------- host-side launch ------------------------------------------
static float* symf(const void* sym) {
    void* p = nullptr;
    cudaGetSymbolAddress(&p, sym);
    return (float*)p;
}
static int* symi(const void* sym) {
    void* p = nullptr;
    cudaGetSymbolAddress(&p, sym);
    return (int*)p;
}
static __nv_bfloat16* symb(const void* sym) {
    void* p = nullptr;
    cudaGetSymbolAddress(&p, sym);
    return (__nv_bfloat16*)p;
}

extern "C" void kernel_launch(void* const* d_in, const int* in_sizes, int n_in,
                              void* d_out, int out_size) {
    const int*   z        = (const int*)  d_in[0];
    const float* pos      = (const float*)d_in[1];
    const int*   edge_src = (const int*)  d_in[2];
    const int*   edge_dst = (const int*)  d_in[3];
    const int*   mol_idx  = (const int*)  d_in[4];
    const float* embed    = (const float*)d_in[5];
    const float* msg_w1   = (const float*)d_in[6];
    const float* msg_b1   = (const float*)d_in[7];
    const float* msg_w2   = (const float*)d_in[8];
    const float* msg_b2   = (const float*)d_in[9];
    const float* rbf_w    = (const float*)d_in[10];
    const float* rbf_b    = (const float*)d_in[11];
    const float* upd_u    = (const float*)d_in[12];
    const float* upd_v    = (const float*)d_in[13];
    const float* upd_a1   = (const float*)d_in[14];
    const float* upd_a1b  = (const float*)d_in[15];
    const float* upd_a2   = (const float*)d_in[16];
    const float* upd_a2b  = (const float*)d_in[17];
    const float* out_w1   = (const float*)d_in[18];
    const float* out_b1   = (const float*)d_in[19];
    const float* out_w2   = (const float*)d_in[20];
    const float* out_b2   = (const float*)d_in[21];
    float* out = (float*)d_out;

    float* s    = symf(g_s);
    float* vA   = symf(g_vA);
    float* vB   = symf(g_vB);
    float* h    = symf(g_h);
    float* phi  = symf(g_phi);
    float* uvv  = symf(g_uvv);
    float* cat  = symf(g_cat);
    float* ah   = symf(g_ah);
    float* a    = symf(g_a);
    float* egeo = symf(g_egeo);
    int* esrc   = symi(g_esrc);
    int* rowst  = symi(g_rowstart);
    int* cursor = symi(g_cursor);
    int* count  = symi(g_count);
    __nv_bfloat16* whi = symb(g_whi);
    __nv_bfloat16* wlo = symb(g_wlo);

    cudaFuncSetAttribute(gemm_mma<true>,  cudaFuncAttributeMaxDynamicSharedMemorySize, GT_SMEM);
    cudaFuncSetAttribute(gemm_mma<false>, cudaFuncAttributeMaxDynamicSharedMemorySize, GT_SMEM);

    // init + weight prep (single launch)
    init_kernel<<<(NA + 255) / 256, 256>>>(count, out);
    embed_kernel<<<(NA * 32 + 255) / 256, 256>>>(z, embed, s);
    wprep_all<<<(557056 + 255) / 256, 256>>>(msg_w1, msg_w2, upd_u, upd_v,
                                             upd_a1, upd_a2, out_w1, whi, wlo);

    // CSR + edge geometry
    count_kernel<<<(NE + 255) / 256, 256>>>(edge_dst, count);
    scan_kernel<<<1, 1024>>>(count, rowst, cursor);
    fill_kernel<<<(NE + 255) / 256, 256>>>(edge_src, edge_dst, pos, cursor, egeo, esrc);

    for (int l = 0; l < LL; l++) {
        size_t LB = (size_t)l * 180224;
        const float* bb1 = msg_b1  + (size_t)l * FF;
        const float* bb2 = msg_b2  + (size_t)l * 3 * FF;
        const float* rw  = rbf_w   + (size_t)l * RR * 3 * FF;
        const float* rb  = rbf_b   + (size_t)l * 3 * FF;
        const float* a1b = upd_a1b + (size_t)l * FF;
        const float* a2b = upd_a2b + (size_t)l * 3 * FF;

        gemm_mma<true ><<<dim3(2, 64),  256, GT_SMEM>>>(s,   whi + LB,          wlo + LB,          bb1,     h,   NA, 128, 128);
        gemm_mma<false><<<dim3(6, 64),  256, GT_SMEM>>>(h,   whi + LB + 16384,  wlo + LB + 16384,  bb2,     phi, NA, 384, 128);
        if (l == 0)
            msg_kernel<true ><<<NA / APB, 64>>>(phi, vA, s, vB, rw, rb, egeo, esrc, rowst);
        else
            msg_kernel<false><<<NA / APB, 64>>>(phi, vA, s, vB, rw, rb, egeo, esrc, rowst);
        gemm_mma<false><<<dim3(4, 192), 256, GT_SMEM>>>(vB,  whi + LB + 65536,  wlo + LB + 65536,  nullptr, uvv, NA * 3, 256, 128);
        cat_kernel<<<(NA * FF + 255) / 256, 256>>>(s, uvv, cat);
        gemm_mma<true ><<<dim3(2, 64),  256, GT_SMEM>>>(cat, whi + LB + 98304,  wlo + LB + 98304,  a1b,     ah,  NA, 128, 256);
        gemm_mma<false><<<dim3(6, 64),  256, GT_SMEM>>>(ah,  whi + LB + 131072, wlo + LB + 131072, a2b,     a,   NA, 384, 128);
        upd_kernel<<<(NA * FF + 255) / 256, 256>>>(uvv, a, s, vB, vA);
    }

    gemm_mma<true><<<dim3(2, 64), 256, GT_SMEM>>>(s, whi + 540672, wlo + 540672, out_b1, h, NA, 128, 128);
    out2_kernel<<<NA * 32 / 256, 256>>>(h, out_w2, out_b2, mol_idx, out);
}